// round 13
// baseline (speedup 1.0000x reference)
#include <cuda_runtime.h>
#include <cuda_fp16.h>
#include <cuda_bf16.h>
#include <math.h>
#include <stddef.h>
#include <stdint.h>

// Problem dims (fixed)
constexpr int B_  = 64;
constexpr int T_  = 512;
constexpr int D_  = 512;
constexpr int H_  = 512;
constexpr int G_  = 2048;              // 4*H gates (i,f,g,o)
constexpr int BT_ = B_ * T_;           // 32768
constexpr size_t BTG_ = (size_t)BT_ * G_;   // 67108864 per direction
constexpr int BH_ = B_ * H_;           // 32768

// Scratch (device globals; referenced ONLY from device code — host-side
// references to __device__ symbols give the host shadow address, the R6 bug).
__device__ float g_zx[2 * 67108864];        // [dir][B*T][G] gate preactivations
__device__ float g_h0[33554432];            // layer-0 output [B][T][2H]

// fp16 single-pass GEMM operands
__device__ __align__(16) __half g_Ah[33554432];      // [M, K<=1024]
__device__ __align__(16) __half g_Bh[2][2097152];    // [slot][N=2048, K<=1024]

// Recurrent h state, bf16 hi/lo, ping-ponged: [dir][ping][hi/lo][B*H]
__device__ __align__(16) __nv_bfloat16 g_hb[2][2][2][32768];

// Per-direction software grid barriers (64 co-resident blocks each; padded)
__device__ unsigned g_bar_cnt[2][32];
__device__ volatile unsigned g_bar_ph[2][32];

__device__ __forceinline__ void grid_barrier_dir(int dir)
{
    __syncthreads();
    if (threadIdx.x == 0) {
        unsigned gen = g_bar_ph[dir][0];
        __threadfence();
        if (atomicAdd(&g_bar_cnt[dir][0], 1u) == 63u) {
            g_bar_cnt[dir][0] = 0;
            __threadfence();
            g_bar_ph[dir][0] = gen + 1u;
        } else {
            while (g_bar_ph[dir][0] == gen) __nanosleep(64);
            __threadfence();
        }
    }
    __syncthreads();
}

// ---------------------------------------------------------------------------
// Baseline-PTX helpers (compute_103-safe: ldmatrix + mma.sync + cp.async)
// ---------------------------------------------------------------------------
__device__ __forceinline__ uint32_t smem_u32(const void* p) {
    uint32_t a;
    asm("{ .reg .u64 t; cvta.to.shared.u64 t, %1; cvt.u32.u64 %0, t; }" : "=r"(a) : "l"(p));
    return a;
}

__device__ __forceinline__ void ldsm_x4(uint32_t& r0, uint32_t& r1,
                                        uint32_t& r2, uint32_t& r3, uint32_t addr)
{
    asm volatile("ldmatrix.sync.aligned.m8n8.x4.shared.b16 {%0,%1,%2,%3}, [%4];"
        : "=r"(r0), "=r"(r1), "=r"(r2), "=r"(r3) : "r"(addr));
}

__device__ __forceinline__ void mma_16816_f16(float* c, const uint32_t* a,
                                              uint32_t b0, uint32_t b1)
{
    asm volatile(
        "mma.sync.aligned.m16n8k16.row.col.f32.f16.f16.f32 "
        "{%0,%1,%2,%3}, {%4,%5,%6,%7}, {%8,%9}, {%0,%1,%2,%3};"
        : "+f"(c[0]), "+f"(c[1]), "+f"(c[2]), "+f"(c[3])
        : "r"(a[0]), "r"(a[1]), "r"(a[2]), "r"(a[3]), "r"(b0), "r"(b1));
}

__device__ __forceinline__ void mma_16816_bf16(float* c, const uint32_t* a,
                                               uint32_t b0, uint32_t b1)
{
    asm volatile(
        "mma.sync.aligned.m16n8k16.row.col.f32.bf16.bf16.f32 "
        "{%0,%1,%2,%3}, {%4,%5,%6,%7}, {%8,%9}, {%0,%1,%2,%3};"
        : "+f"(c[0]), "+f"(c[1]), "+f"(c[2]), "+f"(c[3])
        : "r"(a[0]), "r"(a[1]), "r"(a[2]), "r"(a[3]), "r"(b0), "r"(b1));
}

__device__ __forceinline__ void cp_async16(uint32_t dst, const void* src) {
    asm volatile("cp.async.cg.shared.global [%0], [%1], 16;" :: "r"(dst), "l"(src));
}
__device__ __forceinline__ void cp_commit() {
    asm volatile("cp.async.commit_group;" ::: "memory");
}
template <int N>
__device__ __forceinline__ void cp_wait() {
    asm volatile("cp.async.wait_group %0;" :: "n"(N) : "memory");
}

// ---------------------------------------------------------------------------
// Convert fp32 -> fp16 into g_Ah. srcSel: 0 = ext ptr, 1 = g_h0.
// ---------------------------------------------------------------------------
__global__ void convertA_kernel(const float4* __restrict__ srcExt, int srcSel, int n4)
{
    int i = blockIdx.x * 256 + threadIdx.x;
    if (i >= n4) return;
    const float4* src = srcSel ? (const float4*)g_h0 : srcExt;
    float4 v = src[i];
    __half2* hp = (__half2*)(g_Ah + 4 * (size_t)i);
    hp[0] = __half2(__float2half_rn(v.x), __float2half_rn(v.y));
    hp[1] = __half2(__float2half_rn(v.z), __float2half_rn(v.w));
}

// Transpose + convert both W's [K, N=2048] fp32 -> g_Bh[slot] [N, K] fp16
__global__ void convertW2_kernel(const float* __restrict__ Wf,
                                 const float* __restrict__ Wb, int K)
{
    int slot = blockIdx.y;
    const float* W = slot ? Wb : Wf;
    int idx = blockIdx.x * 256 + threadIdx.x;      // over K*2048
    if (idx >= K * G_) return;
    int k = idx >> 11;
    int n = idx & 2047;
    g_Bh[slot][(size_t)n * K + k] = __float2half_rn(W[idx]);
}

// ---------------------------------------------------------------------------
// cp.async double-buffered single-pass fp16 mma GEMM (proven core).
// gridDim.z = 2 runs fwd/bwd in one launch. 128x128 tile, BK=32, 8 warps.
// ---------------------------------------------------------------------------
constexpr int TILE_B   = 128 * 80;        // 10240 bytes per tile
constexpr int STAGE_B  = 2 * TILE_B;      // 20480
constexpr int GEMM_SMEM_B = 2 * STAGE_B;  // 40960 (<48KB, no opt-in needed)

__device__ __forceinline__ void stage_loads(
    uint32_t sbase, const __half* __restrict__ Bp,
    int bm, int bn, int K, int k0, int tid)
{
    #pragma unroll
    for (int it = 0; it < 2; it++) {
        int idx = tid + it * 256;          // 0..511 granules of 16B per tile
        int r = idx >> 2, q = idx & 3;
        uint32_t d = sbase + (uint32_t)(r * 80 + q * 16);
        cp_async16(d + 0 * TILE_B, g_Ah + (size_t)(bm + r) * K + k0 + q * 8);
        cp_async16(d + 1 * TILE_B, Bp   + (size_t)(bn + r) * K + k0 + q * 8);
    }
}

__global__ __launch_bounds__(256) void gemm_mma_kernel(
    const float* __restrict__ bias_f, const float* __restrict__ bias_b, int K)
{
    extern __shared__ char dsm[];
    const uint32_t sb = smem_u32(dsm);

    const int bslot = blockIdx.z;
    const float* bias = bslot ? bias_b : bias_f;
    const int tid = threadIdx.x;
    const int wid = tid >> 5, lane = tid & 31;
    const int warp_m = wid >> 2;          // 0..1
    const int warp_n = wid & 3;           // 0..3
    const int bn = blockIdx.x * 128;
    const int bm = blockIdx.y * 128;
    float* C = g_zx + (size_t)bslot * BTG_;
    const __half* Bp = g_Bh[bslot];

    float acc[4][4][4];
    #pragma unroll
    for (int mt = 0; mt < 4; mt++)
        #pragma unroll
        for (int nt = 0; nt < 4; nt++)
            #pragma unroll
            for (int q = 0; q < 4; q++) acc[mt][nt][q] = 0.0f;

    const int a_row = warp_m * 64 + (lane & 15);
    const int a_col = (lane >> 4) * 8;
    const int b_row = warp_n * 32 + (lane & 7) + ((lane >> 4) & 1) * 8;
    const int b_col = ((lane >> 3) & 1) * 8;

    const int nchunk = K / 32;

    stage_loads(sb, Bp, bm, bn, K, 0, tid);
    cp_commit();

    for (int ch = 0; ch < nchunk; ch++) {
        if (ch + 1 < nchunk) {
            stage_loads(sb + ((ch + 1) & 1) * STAGE_B, Bp, bm, bn, K, (ch + 1) * 32, tid);
            cp_commit();
            cp_wait<1>();
        } else {
            cp_wait<0>();
        }
        __syncthreads();

        const uint32_t stg = sb + (ch & 1) * STAGE_B;
        const uint32_t a_b = stg;
        const uint32_t b_b = stg + TILE_B;

        #pragma unroll
        for (int kk = 0; kk < 2; kk++) {
            const int k16 = kk * 16;
            uint32_t af[4][4];
            #pragma unroll
            for (int mt = 0; mt < 4; mt++) {
                uint32_t off = (uint32_t)((a_row + mt * 16) * 40 + k16 + a_col) * 2;
                ldsm_x4(af[mt][0], af[mt][1], af[mt][2], af[mt][3], a_b + off);
            }
            uint32_t bf[4][2];
            #pragma unroll
            for (int np = 0; np < 2; np++) {
                uint32_t off = (uint32_t)((b_row + np * 16) * 40 + k16 + b_col) * 2;
                ldsm_x4(bf[np*2][0], bf[np*2][1], bf[np*2+1][0], bf[np*2+1][1], b_b + off);
            }
            #pragma unroll
            for (int mt = 0; mt < 4; mt++)
                #pragma unroll
                for (int nt = 0; nt < 4; nt++)
                    mma_16816_f16(acc[mt][nt], af[mt], bf[nt][0], bf[nt][1]);
        }
        __syncthreads();
    }

    #pragma unroll
    for (int mt = 0; mt < 4; mt++) {
        const int row0 = bm + warp_m * 64 + mt * 16 + (lane >> 2);
        #pragma unroll
        for (int nt = 0; nt < 4; nt++) {
            const int col = bn + warp_n * 32 + nt * 8 + (lane & 3) * 2;
            const float bv0 = bias[col], bv1 = bias[col + 1];
            float2 v0, v1;
            v0.x = acc[mt][nt][0] + bv0; v0.y = acc[mt][nt][1] + bv1;
            v1.x = acc[mt][nt][2] + bv0; v1.y = acc[mt][nt][3] + bv1;
            *(float2*)&C[(size_t)row0 * G_ + col]       = v0;
            *(float2*)&C[(size_t)(row0 + 8) * G_ + col] = v1;
        }
    }
}

// ---------------------------------------------------------------------------
// Persistent recurrent kernel, tensor-core + gate-interleaved registers.
// Grid (64 jt, 2 dir), 256 threads = 8 warps as 4m x 2n.
// U smem column order c' = (j/4)*16 + (gate/2)*8 + 2*(j%4) + (gate%2), so a
// thread's two acc fragments hold (i,f) and (g,o) for ONE j and rows b, b+8:
// the pointwise update runs out of registers (no z smem exchange).
// K processed in 2 chunks of 256, both prefetched right after the barrier.
// ---------------------------------------------------------------------------
constexpr int U_ST = 520;                         // U smem stride (elements)
constexpr int H_ST = 264;                         // h chunk stride (elements)
constexpr int U_COPY_B  = 32 * U_ST * 2;          // 33280 (one of hi/lo)
constexpr int H_COPY_B  = 64 * H_ST * 2;          // 33792 (one of hi/lo)
constexpr int H_STAGE_B = 2 * H_COPY_B;           // 67584
constexpr int SM_H = 2 * U_COPY_B;                // 66560
constexpr int LSTM_SMEM_B = SM_H + 2 * H_STAGE_B; // 201728

__device__ __forceinline__ void issue_h256(
    uint32_t dst_base, const __nv_bfloat16* __restrict__ hhi,
    const __nv_bfloat16* __restrict__ hlo, int ck, int tid)
{
    #pragma unroll
    for (int it = 0; it < 8; it++) {
        int idx = tid + it * 256;            // 0..2047
        int row = idx >> 5, g = idx & 31;    // 32 granules x 16B = 256 bf16/row
        uint32_t d = dst_base + (uint32_t)(row * 528 + g * 16);
        const size_t s = (size_t)row * H_ + ck * 256 + g * 8;
        cp_async16(d, hhi + s);
        cp_async16(d + H_COPY_B, hlo + s);
    }
}

__global__ __launch_bounds__(256) void lstm_seq_kernel(
    const float* __restrict__ Uf, const float* __restrict__ Ub,
    float* __restrict__ outp)
{
    extern __shared__ char sm[];
    const uint32_t sb = smem_u32(sm);
    const int dir = blockIdx.y;
    const int jt  = blockIdx.x;
    const int tid = threadIdx.x;
    const int wid = tid >> 5, lane = tid & 31;
    const int warp_m = wid >> 1;             // 0..3 (16 batch rows each)
    const int warp_n = wid & 1;              // 0..1 (j-group of 4)

    __nv_bfloat16* Uhi_s = (__nv_bfloat16*)sm;
    __nv_bfloat16* Ulo_s = Uhi_s + 32 * U_ST;
    const uint32_t u_hi = sb;
    const uint32_t u_lo = sb + U_COPY_B;
    const uint32_t h_b  = sb + SM_H;

    const float* U_raw = dir ? Ub : Uf;
    float* out = outp ? outp : g_h0;
    const float* zx_d = g_zx + (size_t)dir * BTG_;

    // One-time: U -> smem bf16 hi/lo with gate-interleaved column order.
    // c' decode: jhi=c>>4, n8=(c>>3)&1, jlo=(c&7)>>1, bit=c&1
    //   gate = n8*2 + bit, j_local = jhi*4 + jlo
    #pragma unroll 4
    for (int p = 0; p < 64; p++) {
        int idx = tid + p * 256;             // k*32 + c over 512*32
        int k = idx >> 5, c = idx & 31;
        int gate = ((c >> 3) & 1) * 2 + (c & 1);
        int jl   = (c >> 4) * 4 + ((c & 7) >> 1);
        float v = U_raw[(size_t)k * G_ + gate * H_ + jt * 8 + jl];
        __nv_bfloat16 h = __float2bfloat16(v);
        Uhi_s[c * U_ST + k] = h;
        Ulo_s[c * U_ST + k] = __float2bfloat16(v - __bfloat162float(h));
    }
    // Zero own slice of h ping slot 0
    for (int i = tid; i < 512; i += 256) {
        int b = i >> 3, jl = i & 7;
        g_hb[dir][0][0][b * H_ + jt * 8 + jl] = __float2bfloat16(0.0f);
        g_hb[dir][0][1][b * H_ + jt * 8 + jl] = __float2bfloat16(0.0f);
    }
    __syncthreads();
    grid_barrier_dir(dir);

    // Thread owns (b0 = warp_m*16 + lane/4, b1 = b0+8, j = warp_n*4 + lane%4)
    const int brow0 = warp_m * 16 + (lane >> 2);
    const int jl = warp_n * 4 + (lane & 3);
    const int j = jt * 8 + jl;
    float creg[2] = {0.0f, 0.0f};

    // ldmatrix lane addressing (element units)
    const int a_row = warp_m * 16 + (lane & 15);
    const int a_col = (lane >> 4) * 8;
    const int b_row = warp_n * 16 + (lane & 7) + ((lane >> 4) & 1) * 8;
    const int b_col = ((lane >> 3) & 1) * 8;

    for (int t = 0; t < T_; t++) {
        const int tt = dir ? (T_ - 1 - t) : t;
        const int ping = t & 1, pnext = ping ^ 1;
        const __nv_bfloat16* hhi = g_hb[dir][ping][0];
        const __nv_bfloat16* hlo = g_hb[dir][ping][1];

        // Prefetch both K-chunks immediately
        issue_h256(h_b, hhi, hlo, 0, tid);
        cp_commit();
        issue_h256(h_b + H_STAGE_B, hhi, hlo, 1, tid);
        cp_commit();

        // zx gate prefetch (overlaps cp.async)
        float zpre[2][4];
        #pragma unroll
        for (int r = 0; r < 2; r++) {
            const int b = brow0 + r * 8;
            const float* zp = zx_d + ((size_t)b * T_ + tt) * G_;
            #pragma unroll
            for (int g = 0; g < 4; g++) zpre[r][g] = zp[g * H_ + j];
        }

        float acc[2][4];
        #pragma unroll
        for (int nt = 0; nt < 2; nt++)
            #pragma unroll
            for (int q = 0; q < 4; q++) acc[nt][q] = 0.0f;

        #pragma unroll
        for (int ck = 0; ck < 2; ck++) {
            if (ck == 0) cp_wait<1>(); else cp_wait<0>();
            __syncthreads();

            const uint32_t ha = h_b + ck * H_STAGE_B;
            const uint32_t la = ha + H_COPY_B;
            const int kbase = ck * 256;

            #pragma unroll
            for (int ks = 0; ks < 16; ks++) {
                const int k16 = ks * 16;
                const uint32_t aoff = (uint32_t)(a_row * H_ST + k16 + a_col) * 2;
                uint32_t ahi[4], alo[4];
                ldsm_x4(ahi[0], ahi[1], ahi[2], ahi[3], ha + aoff);
                ldsm_x4(alo[0], alo[1], alo[2], alo[3], la + aoff);
                const uint32_t boff =
                    (uint32_t)(b_row * U_ST + kbase + k16 + b_col) * 2;
                uint32_t bh[4], bl[4];
                ldsm_x4(bh[0], bh[1], bh[2], bh[3], u_hi + boff);
                ldsm_x4(bl[0], bl[1], bl[2], bl[3], u_lo + boff);
                mma_16816_bf16(acc[0], ahi, bh[0], bh[1]);
                mma_16816_bf16(acc[1], ahi, bh[2], bh[3]);
                mma_16816_bf16(acc[0], ahi, bl[0], bl[1]);
                mma_16816_bf16(acc[1], ahi, bl[2], bl[3]);
                mma_16816_bf16(acc[0], alo, bh[0], bh[1]);
                mma_16816_bf16(acc[1], alo, bh[2], bh[3]);
            }
            __syncthreads();
        }

        // Pointwise straight out of registers:
        // acc[0] = (i,f), acc[1] = (g,o); q0,q1 -> row brow0; q2,q3 -> +8.
        #pragma unroll
        for (int r = 0; r < 2; r++) {
            const int b = brow0 + r * 8;
            const float zi = acc[0][r * 2 + 0] + zpre[r][0];
            const float zf = acc[0][r * 2 + 1] + zpre[r][1];
            const float zg = acc[1][r * 2 + 0] + zpre[r][2];
            const float zo = acc[1][r * 2 + 1] + zpre[r][3];
            const float ig = 1.0f / (1.0f + expf(-zi));
            const float fg = 1.0f / (1.0f + expf(-zf));
            const float gg = tanhf(zg);
            const float og = 1.0f / (1.0f + expf(-zo));
            const float cn = fg * creg[r] + ig * gg;
            const float hn = og * tanhf(cn);
            creg[r] = cn;
            out[((size_t)b * T_ + tt) * (2 * H_) + dir * H_ + j] = hn;
            const __nv_bfloat16 hh = __float2bfloat16(hn);
            g_hb[dir][pnext][0][b * H_ + j] = hh;
            g_hb[dir][pnext][1][b * H_ + j] =
                __float2bfloat16(hn - __bfloat162float(hh));
        }

        grid_barrier_dir(dir);
    }
}

// ---------------------------------------------------------------------------
extern "C" void kernel_launch(void* const* d_in, const int* in_sizes, int n_in,
                              void* d_out, int out_size)
{
    (void)in_sizes; (void)n_in; (void)out_size;
    const float* x   = (const float*)d_in[0];
    const float* W0f = (const float*)d_in[1];
    const float* U0f = (const float*)d_in[2];
    const float* b0f = (const float*)d_in[3];
    const float* W0b = (const float*)d_in[4];
    const float* U0b = (const float*)d_in[5];
    const float* b0b = (const float*)d_in[6];
    const float* W1f = (const float*)d_in[7];
    const float* U1f = (const float*)d_in[8];
    const float* b1f = (const float*)d_in[9];
    const float* W1b = (const float*)d_in[10];
    const float* U1b = (const float*)d_in[11];
    const float* b1b = (const float*)d_in[12];
    float* out = (float*)d_out;

    // Opt-in for ~197KB lstm smem (idempotent; not an allocation)
    cudaFuncSetAttribute(lstm_seq_kernel,
                         cudaFuncAttributeMaxDynamicSharedMemorySize, LSTM_SMEM_B);

    dim3 gemmGrid(G_ / 128, BT_ / 128, 2);   // fwd+bwd fused
    dim3 seqGrid(64, 2);

    // ---- Phase 0: layer 0 (input = x, K = 512) ----
    {
        const int n4 = (BT_ * D_) / 4;
        convertA_kernel<<<(n4 + 255) / 256, 256>>>((const float4*)x, 0, n4);
        convertW2_kernel<<<dim3((D_ * G_ + 255) / 256, 2), 256>>>(W0f, W0b, D_);
        gemm_mma_kernel<<<gemmGrid, 256, GEMM_SMEM_B>>>(b0f, b0b, D_);
        lstm_seq_kernel<<<seqGrid, 256, LSTM_SMEM_B>>>(U0f, U0b, (float*)nullptr);
    }

    // ---- Phase 1: layer 1 (input = g_h0, K = 1024) ----
    {
        const int K1 = 2 * H_;
        const int n4 = (BT_ * K1) / 4;
        convertA_kernel<<<(n4 + 255) / 256, 256>>>((const float4*)nullptr, 1, n4);
        convertW2_kernel<<<dim3((K1 * G_ + 255) / 256, 2), 256>>>(W1f, W1b, K1);
        gemm_mma_kernel<<<gemmGrid, 256, GEMM_SMEM_B>>>(b1f, b1b, K1);
        lstm_seq_kernel<<<seqGrid, 256, LSTM_SMEM_B>>>(U1f, U1b, out);
    }
}

// round 14
// speedup vs baseline: 1.0547x; 1.0547x over previous
#include <cuda_runtime.h>
#include <cuda_fp16.h>
#include <cuda_bf16.h>
#include <math.h>
#include <stddef.h>
#include <stdint.h>

// Problem dims (fixed)
constexpr int B_  = 64;
constexpr int T_  = 512;
constexpr int D_  = 512;
constexpr int H_  = 512;
constexpr int G_  = 2048;              // 4*H gates (i,f,g,o)
constexpr int BT_ = B_ * T_;           // 32768
constexpr size_t BTG_ = (size_t)BT_ * G_;   // 67108864 per direction
constexpr int BH_ = B_ * H_;           // 32768

// Scratch (device globals; referenced ONLY from device code — host-side
// references to __device__ symbols give the host shadow address, the R6 bug).
__device__ float g_zx[2 * 67108864];        // [dir][B*T][G] gate preactivations
__device__ float g_h0[33554432];            // layer-0 output [B][T][2H]

// fp16 single-pass GEMM operands
__device__ __align__(16) __half g_Ah[33554432];      // [M, K<=1024]
__device__ __align__(16) __half g_Bh[2][2097152];    // [slot][N=2048, K<=1024]

// Recurrent h state, bf16 hi/lo, ping-ponged: [dir][ping][hi/lo][B*H]
__device__ __align__(16) __nv_bfloat16 g_hb[2][2][2][32768];

// Per-direction software grid barriers (64 co-resident blocks each; padded)
__device__ unsigned g_bar_cnt[2][32];
__device__ volatile unsigned g_bar_ph[2][32];

__device__ __forceinline__ void grid_barrier_dir(int dir)
{
    __syncthreads();
    if (threadIdx.x == 0) {
        unsigned gen = g_bar_ph[dir][0];
        __threadfence();
        if (atomicAdd(&g_bar_cnt[dir][0], 1u) == 63u) {
            g_bar_cnt[dir][0] = 0;
            __threadfence();
            g_bar_ph[dir][0] = gen + 1u;
        } else {
            while (g_bar_ph[dir][0] == gen) __nanosleep(64);
            __threadfence();
        }
    }
    __syncthreads();
}

// ---------------------------------------------------------------------------
// Baseline-PTX helpers (compute_103-safe: ldmatrix + mma.sync + cp.async)
// ---------------------------------------------------------------------------
__device__ __forceinline__ uint32_t smem_u32(const void* p) {
    uint32_t a;
    asm("{ .reg .u64 t; cvta.to.shared.u64 t, %1; cvt.u32.u64 %0, t; }" : "=r"(a) : "l"(p));
    return a;
}

__device__ __forceinline__ void ldsm_x4(uint32_t& r0, uint32_t& r1,
                                        uint32_t& r2, uint32_t& r3, uint32_t addr)
{
    asm volatile("ldmatrix.sync.aligned.m8n8.x4.shared.b16 {%0,%1,%2,%3}, [%4];"
        : "=r"(r0), "=r"(r1), "=r"(r2), "=r"(r3) : "r"(addr));
}

__device__ __forceinline__ void mma_16816_f16(float* c, const uint32_t* a,
                                              uint32_t b0, uint32_t b1)
{
    asm volatile(
        "mma.sync.aligned.m16n8k16.row.col.f32.f16.f16.f32 "
        "{%0,%1,%2,%3}, {%4,%5,%6,%7}, {%8,%9}, {%0,%1,%2,%3};"
        : "+f"(c[0]), "+f"(c[1]), "+f"(c[2]), "+f"(c[3])
        : "r"(a[0]), "r"(a[1]), "r"(a[2]), "r"(a[3]), "r"(b0), "r"(b1));
}

__device__ __forceinline__ void mma_16816_bf16(float* c, const uint32_t* a,
                                               uint32_t b0, uint32_t b1)
{
    asm volatile(
        "mma.sync.aligned.m16n8k16.row.col.f32.bf16.bf16.f32 "
        "{%0,%1,%2,%3}, {%4,%5,%6,%7}, {%8,%9}, {%0,%1,%2,%3};"
        : "+f"(c[0]), "+f"(c[1]), "+f"(c[2]), "+f"(c[3])
        : "r"(a[0]), "r"(a[1]), "r"(a[2]), "r"(a[3]), "r"(b0), "r"(b1));
}

__device__ __forceinline__ void cp_async16(uint32_t dst, const void* src) {
    asm volatile("cp.async.cg.shared.global [%0], [%1], 16;" :: "r"(dst), "l"(src));
}
__device__ __forceinline__ void cp_commit() {
    asm volatile("cp.async.commit_group;" ::: "memory");
}
template <int N>
__device__ __forceinline__ void cp_wait() {
    asm volatile("cp.async.wait_group %0;" :: "n"(N) : "memory");
}

// ---------------------------------------------------------------------------
// Convert fp32 -> fp16 into g_Ah. srcSel: 0 = ext ptr, 1 = g_h0.
// ---------------------------------------------------------------------------
__global__ void convertA_kernel(const float4* __restrict__ srcExt, int srcSel, int n4)
{
    int i = blockIdx.x * 256 + threadIdx.x;
    if (i >= n4) return;
    const float4* src = srcSel ? (const float4*)g_h0 : srcExt;
    float4 v = src[i];
    __half2* hp = (__half2*)(g_Ah + 4 * (size_t)i);
    hp[0] = __half2(__float2half_rn(v.x), __float2half_rn(v.y));
    hp[1] = __half2(__float2half_rn(v.z), __float2half_rn(v.w));
}

// Transpose + convert both W's [K, N=2048] fp32 -> g_Bh[slot] [N, K] fp16
__global__ void convertW2_kernel(const float* __restrict__ Wf,
                                 const float* __restrict__ Wb, int K)
{
    int slot = blockIdx.y;
    const float* W = slot ? Wb : Wf;
    int idx = blockIdx.x * 256 + threadIdx.x;      // over K*2048
    if (idx >= K * G_) return;
    int k = idx >> 11;
    int n = idx & 2047;
    g_Bh[slot][(size_t)n * K + k] = __float2half_rn(W[idx]);
}

// ---------------------------------------------------------------------------
// cp.async double-buffered single-pass fp16 mma GEMM (proven core).
// gridDim.z = 2 runs fwd/bwd in one launch. 128x128 tile, BK=32, 8 warps.
// ---------------------------------------------------------------------------
constexpr int TILE_B   = 128 * 80;        // 10240 bytes per tile
constexpr int STAGE_B  = 2 * TILE_B;      // 20480
constexpr int GEMM_SMEM_B = 2 * STAGE_B;  // 40960 (<48KB, no opt-in needed)

__device__ __forceinline__ void stage_loads(
    uint32_t sbase, const __half* __restrict__ Bp,
    int bm, int bn, int K, int k0, int tid)
{
    #pragma unroll
    for (int it = 0; it < 2; it++) {
        int idx = tid + it * 256;          // 0..511 granules of 16B per tile
        int r = idx >> 2, q = idx & 3;
        uint32_t d = sbase + (uint32_t)(r * 80 + q * 16);
        cp_async16(d + 0 * TILE_B, g_Ah + (size_t)(bm + r) * K + k0 + q * 8);
        cp_async16(d + 1 * TILE_B, Bp   + (size_t)(bn + r) * K + k0 + q * 8);
    }
}

__global__ __launch_bounds__(256) void gemm_mma_kernel(
    const float* __restrict__ bias_f, const float* __restrict__ bias_b, int K)
{
    extern __shared__ char dsm[];
    const uint32_t sb = smem_u32(dsm);

    const int bslot = blockIdx.z;
    const float* bias = bslot ? bias_b : bias_f;
    const int tid = threadIdx.x;
    const int wid = tid >> 5, lane = tid & 31;
    const int warp_m = wid >> 2;          // 0..1
    const int warp_n = wid & 3;           // 0..3
    const int bn = blockIdx.x * 128;
    const int bm = blockIdx.y * 128;
    float* C = g_zx + (size_t)bslot * BTG_;
    const __half* Bp = g_Bh[bslot];

    float acc[4][4][4];
    #pragma unroll
    for (int mt = 0; mt < 4; mt++)
        #pragma unroll
        for (int nt = 0; nt < 4; nt++)
            #pragma unroll
            for (int q = 0; q < 4; q++) acc[mt][nt][q] = 0.0f;

    const int a_row = warp_m * 64 + (lane & 15);
    const int a_col = (lane >> 4) * 8;
    const int b_row = warp_n * 32 + (lane & 7) + ((lane >> 4) & 1) * 8;
    const int b_col = ((lane >> 3) & 1) * 8;

    const int nchunk = K / 32;

    stage_loads(sb, Bp, bm, bn, K, 0, tid);
    cp_commit();

    for (int ch = 0; ch < nchunk; ch++) {
        if (ch + 1 < nchunk) {
            stage_loads(sb + ((ch + 1) & 1) * STAGE_B, Bp, bm, bn, K, (ch + 1) * 32, tid);
            cp_commit();
            cp_wait<1>();
        } else {
            cp_wait<0>();
        }
        __syncthreads();

        const uint32_t stg = sb + (ch & 1) * STAGE_B;
        const uint32_t a_b = stg;
        const uint32_t b_b = stg + TILE_B;

        #pragma unroll
        for (int kk = 0; kk < 2; kk++) {
            const int k16 = kk * 16;
            uint32_t af[4][4];
            #pragma unroll
            for (int mt = 0; mt < 4; mt++) {
                uint32_t off = (uint32_t)((a_row + mt * 16) * 40 + k16 + a_col) * 2;
                ldsm_x4(af[mt][0], af[mt][1], af[mt][2], af[mt][3], a_b + off);
            }
            uint32_t bf[4][2];
            #pragma unroll
            for (int np = 0; np < 2; np++) {
                uint32_t off = (uint32_t)((b_row + np * 16) * 40 + k16 + b_col) * 2;
                ldsm_x4(bf[np*2][0], bf[np*2][1], bf[np*2+1][0], bf[np*2+1][1], b_b + off);
            }
            #pragma unroll
            for (int mt = 0; mt < 4; mt++)
                #pragma unroll
                for (int nt = 0; nt < 4; nt++)
                    mma_16816_f16(acc[mt][nt], af[mt], bf[nt][0], bf[nt][1]);
        }
        __syncthreads();
    }

    #pragma unroll
    for (int mt = 0; mt < 4; mt++) {
        const int row0 = bm + warp_m * 64 + mt * 16 + (lane >> 2);
        #pragma unroll
        for (int nt = 0; nt < 4; nt++) {
            const int col = bn + warp_n * 32 + nt * 8 + (lane & 3) * 2;
            const float bv0 = bias[col], bv1 = bias[col + 1];
            float2 v0, v1;
            v0.x = acc[mt][nt][0] + bv0; v0.y = acc[mt][nt][1] + bv1;
            v1.x = acc[mt][nt][2] + bv0; v1.y = acc[mt][nt][3] + bv1;
            *(float2*)&C[(size_t)row0 * G_ + col]       = v0;
            *(float2*)&C[(size_t)(row0 + 8) * G_ + col] = v1;
        }
    }
}

// ---------------------------------------------------------------------------
// Persistent recurrent kernel: R12's proven 4x128 rolling cp.async pipeline
// + gate-interleaved U columns so the pointwise runs out of registers.
// Grid (64 jt, 2 dir), 256 threads = 8 warps as 4m x 2n.
// U smem column c' = (j/4)*16 + (gate/2)*8 + 2*(j%4) + (gate%2): a thread's
// two acc fragments hold (i,f) and (g,o) for ONE j and rows b, b+8 — no z
// smem exchange, c-state in registers.
// ---------------------------------------------------------------------------
constexpr int U_ST = 520;                         // U smem stride (elements)
constexpr int H_ST = 136;                         // h chunk stride (elements)
constexpr int U_COPY_B  = 32 * U_ST * 2;          // 33280 (one of hi/lo)
constexpr int H_COPY_B  = 64 * H_ST * 2;          // 17408 (one of hi/lo)
constexpr int H_STAGE_B = 2 * H_COPY_B;           // 34816
constexpr int SM_H = 2 * U_COPY_B;                // 66560
constexpr int LSTM_SMEM_B = SM_H + 2 * H_STAGE_B; // 136192

__device__ __forceinline__ void issue_h(
    uint32_t dst_base, const __nv_bfloat16* __restrict__ hhi,
    const __nv_bfloat16* __restrict__ hlo, int ck, int tid)
{
    #pragma unroll
    for (int it = 0; it < 4; it++) {
        int idx = tid + it * 256;            // 0..1023
        int row = idx >> 4, g = idx & 15;    // 16 granules x 16B = 128 bf16/row
        uint32_t d = dst_base + (uint32_t)(row * 272 + g * 16);
        const size_t s = (size_t)row * H_ + ck * 128 + g * 8;
        cp_async16(d, hhi + s);
        cp_async16(d + H_COPY_B, hlo + s);
    }
}

__global__ __launch_bounds__(256) void lstm_seq_kernel(
    const float* __restrict__ Uf, const float* __restrict__ Ub,
    float* __restrict__ outp)
{
    extern __shared__ char sm[];
    const uint32_t sb = smem_u32(sm);
    const int dir = blockIdx.y;
    const int jt  = blockIdx.x;
    const int tid = threadIdx.x;
    const int wid = tid >> 5, lane = tid & 31;
    const int warp_m = wid >> 1;             // 0..3 (16 batch rows each)
    const int warp_n = wid & 1;              // 0..1 (j-group of 4)

    __nv_bfloat16* Uhi_s = (__nv_bfloat16*)sm;
    __nv_bfloat16* Ulo_s = Uhi_s + 32 * U_ST;
    const uint32_t u_hi = sb;
    const uint32_t u_lo = sb + U_COPY_B;
    const uint32_t h_b  = sb + SM_H;

    const float* U_raw = dir ? Ub : Uf;
    float* out = outp ? outp : g_h0;
    const float* zx_d = g_zx + (size_t)dir * BTG_;

    // One-time: U -> smem bf16 hi/lo with gate-interleaved column order.
    // c' decode: gate = ((c>>3)&1)*2 + (c&1), j_local = (c>>4)*4 + ((c&7)>>1)
    #pragma unroll 4
    for (int p = 0; p < 64; p++) {
        int idx = tid + p * 256;             // k*32 + c over 512*32
        int k = idx >> 5, c = idx & 31;
        int gate = ((c >> 3) & 1) * 2 + (c & 1);
        int jl   = (c >> 4) * 4 + ((c & 7) >> 1);
        float v = U_raw[(size_t)k * G_ + gate * H_ + jt * 8 + jl];
        __nv_bfloat16 h = __float2bfloat16(v);
        Uhi_s[c * U_ST + k] = h;
        Ulo_s[c * U_ST + k] = __float2bfloat16(v - __bfloat162float(h));
    }
    // Zero own slice of h ping slot 0
    for (int i = tid; i < 512; i += 256) {
        int b = i >> 3, jl = i & 7;
        g_hb[dir][0][0][b * H_ + jt * 8 + jl] = __float2bfloat16(0.0f);
        g_hb[dir][0][1][b * H_ + jt * 8 + jl] = __float2bfloat16(0.0f);
    }
    __syncthreads();
    grid_barrier_dir(dir);

    // Thread owns (b0 = warp_m*16 + lane/4, b1 = b0+8, j = warp_n*4 + lane%4)
    const int brow0 = warp_m * 16 + (lane >> 2);
    const int jl = warp_n * 4 + (lane & 3);
    const int j = jt * 8 + jl;
    float creg[2] = {0.0f, 0.0f};

    // ldmatrix lane addressing (element units)
    const int a_row = warp_m * 16 + (lane & 15);
    const int a_col = (lane >> 4) * 8;
    const int b_row = warp_n * 16 + (lane & 7) + ((lane >> 4) & 1) * 8;
    const int b_col = ((lane >> 3) & 1) * 8;

    for (int t = 0; t < T_; t++) {
        const int tt = dir ? (T_ - 1 - t) : t;
        const int ping = t & 1, pnext = ping ^ 1;
        const __nv_bfloat16* hhi = g_hb[dir][ping][0];
        const __nv_bfloat16* hlo = g_hb[dir][ping][1];

        // Prefetch zx gates (latency hidden under the mma loop)
        float zpre[2][4];
        #pragma unroll
        for (int r = 0; r < 2; r++) {
            const int b = brow0 + r * 8;
            const float* zp = zx_d + ((size_t)b * T_ + tt) * G_;
            #pragma unroll
            for (int g = 0; g < 4; g++) zpre[r][g] = zp[g * H_ + j];
        }

        issue_h(h_b, hhi, hlo, 0, tid);
        cp_commit();

        float acc[2][4];
        #pragma unroll
        for (int nt = 0; nt < 2; nt++)
            #pragma unroll
            for (int q = 0; q < 4; q++) acc[nt][q] = 0.0f;

        for (int ck = 0; ck < 4; ck++) {
            if (ck + 1 < 4) {
                issue_h(h_b + ((ck + 1) & 1) * H_STAGE_B, hhi, hlo, ck + 1, tid);
                cp_commit();
                cp_wait<1>();
            } else {
                cp_wait<0>();
            }
            __syncthreads();

            const uint32_t ha = h_b + (ck & 1) * H_STAGE_B;
            const uint32_t la = ha + H_COPY_B;
            const int kbase = ck * 128;

            #pragma unroll
            for (int ks = 0; ks < 8; ks++) {
                const int k16 = ks * 16;
                const uint32_t aoff = (uint32_t)(a_row * H_ST + k16 + a_col) * 2;
                uint32_t ahi[4], alo[4];
                ldsm_x4(ahi[0], ahi[1], ahi[2], ahi[3], ha + aoff);
                ldsm_x4(alo[0], alo[1], alo[2], alo[3], la + aoff);
                const uint32_t boff =
                    (uint32_t)(b_row * U_ST + kbase + k16 + b_col) * 2;
                uint32_t bh[4], bl[4];
                ldsm_x4(bh[0], bh[1], bh[2], bh[3], u_hi + boff);
                ldsm_x4(bl[0], bl[1], bl[2], bl[3], u_lo + boff);
                mma_16816_bf16(acc[0], ahi, bh[0], bh[1]);
                mma_16816_bf16(acc[1], ahi, bh[2], bh[3]);
                mma_16816_bf16(acc[0], ahi, bl[0], bl[1]);
                mma_16816_bf16(acc[1], ahi, bl[2], bl[3]);
                mma_16816_bf16(acc[0], alo, bh[0], bh[1]);
                mma_16816_bf16(acc[1], alo, bh[2], bh[3]);
            }
            __syncthreads();
        }

        // Pointwise straight out of registers:
        // acc[0] = (i,f), acc[1] = (g,o); q0,q1 -> row brow0; q2,q3 -> +8.
        #pragma unroll
        for (int r = 0; r < 2; r++) {
            const int b = brow0 + r * 8;
            const float zi = acc[0][r * 2 + 0] + zpre[r][0];
            const float zf = acc[0][r * 2 + 1] + zpre[r][1];
            const float zg = acc[1][r * 2 + 0] + zpre[r][2];
            const float zo = acc[1][r * 2 + 1] + zpre[r][3];
            const float ig = 1.0f / (1.0f + expf(-zi));
            const float fg = 1.0f / (1.0f + expf(-zf));
            const float gg = tanhf(zg);
            const float og = 1.0f / (1.0f + expf(-zo));
            const float cn = fg * creg[r] + ig * gg;
            const float hn = og * tanhf(cn);
            creg[r] = cn;
            out[((size_t)b * T_ + tt) * (2 * H_) + dir * H_ + j] = hn;
            const __nv_bfloat16 hh = __float2bfloat16(hn);
            g_hb[dir][pnext][0][b * H_ + j] = hh;
            g_hb[dir][pnext][1][b * H_ + j] =
                __float2bfloat16(hn - __bfloat162float(hh));
        }

        grid_barrier_dir(dir);
    }
}

// ---------------------------------------------------------------------------
extern "C" void kernel_launch(void* const* d_in, const int* in_sizes, int n_in,
                              void* d_out, int out_size)
{
    (void)in_sizes; (void)n_in; (void)out_size;
    const float* x   = (const float*)d_in[0];
    const float* W0f = (const float*)d_in[1];
    const float* U0f = (const float*)d_in[2];
    const float* b0f = (const float*)d_in[3];
    const float* W0b = (const float*)d_in[4];
    const float* U0b = (const float*)d_in[5];
    const float* b0b = (const float*)d_in[6];
    const float* W1f = (const float*)d_in[7];
    const float* U1f = (const float*)d_in[8];
    const float* b1f = (const float*)d_in[9];
    const float* W1b = (const float*)d_in[10];
    const float* U1b = (const float*)d_in[11];
    const float* b1b = (const float*)d_in[12];
    float* out = (float*)d_out;

    // Opt-in for 133KB lstm smem (idempotent; not an allocation)
    cudaFuncSetAttribute(lstm_seq_kernel,
                         cudaFuncAttributeMaxDynamicSharedMemorySize, LSTM_SMEM_B);

    dim3 gemmGrid(G_ / 128, BT_ / 128, 2);   // fwd+bwd fused
    dim3 seqGrid(64, 2);

    // ---- Phase 0: layer 0 (input = x, K = 512) ----
    {
        const int n4 = (BT_ * D_) / 4;
        convertA_kernel<<<(n4 + 255) / 256, 256>>>((const float4*)x, 0, n4);
        convertW2_kernel<<<dim3((D_ * G_ + 255) / 256, 2), 256>>>(W0f, W0b, D_);
        gemm_mma_kernel<<<gemmGrid, 256, GEMM_SMEM_B>>>(b0f, b0b, D_);
        lstm_seq_kernel<<<seqGrid, 256, LSTM_SMEM_B>>>(U0f, U0b, (float*)nullptr);
    }

    // ---- Phase 1: layer 1 (input = g_h0, K = 1024) ----
    {
        const int K1 = 2 * H_;
        const int n4 = (BT_ * K1) / 4;
        convertA_kernel<<<(n4 + 255) / 256, 256>>>((const float4*)nullptr, 1, n4);
        convertW2_kernel<<<dim3((K1 * G_ + 255) / 256, 2), 256>>>(W1f, W1b, K1);
        gemm_mma_kernel<<<gemmGrid, 256, GEMM_SMEM_B>>>(b1f, b1b, K1);
        lstm_seq_kernel<<<seqGrid, 256, LSTM_SMEM_B>>>(U1f, U1b, out);
    }
}

// round 15
// speedup vs baseline: 1.2018x; 1.1395x over previous
#include <cuda_runtime.h>
#include <cuda_fp16.h>
#include <math.h>
#include <stddef.h>
#include <stdint.h>

// Problem dims (fixed)
constexpr int B_  = 64;
constexpr int T_  = 512;
constexpr int D_  = 512;
constexpr int H_  = 512;
constexpr int G_  = 2048;              // 4*H gates (i,f,g,o)
constexpr int BT_ = B_ * T_;           // 32768
constexpr size_t BTG_ = (size_t)BT_ * G_;   // 67108864 per direction
constexpr int BH_ = B_ * H_;           // 32768

// Scratch (device globals; referenced ONLY from device code — host-side
// references to __device__ symbols give the host shadow address, the R6 bug).
__device__ float g_zx[2 * 67108864];        // [dir][B*T][G] gate preactivations
__device__ float g_h0[33554432];            // layer-0 output [B][T][2H]

// fp16 single-pass GEMM operands
__device__ __align__(16) __half g_Ah[33554432];      // [M, K<=1024]
__device__ __align__(16) __half g_Bh[2][2097152];    // [slot][N=2048, K<=1024]

// Recurrent h state, single fp16, ping-ponged: [dir][ping][B*H]
__device__ __align__(16) __half g_hh[2][2][32768];

// Per-direction software grid barriers (64 co-resident blocks each; padded)
__device__ unsigned g_bar_cnt[2][32];
__device__ volatile unsigned g_bar_ph[2][32];

// ---------------------------------------------------------------------------
// Baseline-PTX helpers (compute_103-safe: ldmatrix + mma.sync + cp.async)
// ---------------------------------------------------------------------------
__device__ __forceinline__ uint32_t smem_u32(const void* p) {
    uint32_t a;
    asm("{ .reg .u64 t; cvta.to.shared.u64 t, %1; cvt.u32.u64 %0, t; }" : "=r"(a) : "l"(p));
    return a;
}

__device__ __forceinline__ void ldsm_x4(uint32_t& r0, uint32_t& r1,
                                        uint32_t& r2, uint32_t& r3, uint32_t addr)
{
    asm volatile("ldmatrix.sync.aligned.m8n8.x4.shared.b16 {%0,%1,%2,%3}, [%4];"
        : "=r"(r0), "=r"(r1), "=r"(r2), "=r"(r3) : "r"(addr));
}

__device__ __forceinline__ void mma_16816_f16(float* c, const uint32_t* a,
                                              uint32_t b0, uint32_t b1)
{
    asm volatile(
        "mma.sync.aligned.m16n8k16.row.col.f32.f16.f16.f32 "
        "{%0,%1,%2,%3}, {%4,%5,%6,%7}, {%8,%9}, {%0,%1,%2,%3};"
        : "+f"(c[0]), "+f"(c[1]), "+f"(c[2]), "+f"(c[3])
        : "r"(a[0]), "r"(a[1]), "r"(a[2]), "r"(a[3]), "r"(b0), "r"(b1));
}

__device__ __forceinline__ void cp_async16(uint32_t dst, const void* src) {
    asm volatile("cp.async.cg.shared.global [%0], [%1], 16;" :: "r"(dst), "l"(src));
}
__device__ __forceinline__ void cp_commit() {
    asm volatile("cp.async.commit_group;" ::: "memory");
}
template <int N>
__device__ __forceinline__ void cp_wait() {
    asm volatile("cp.async.wait_group %0;" :: "n"(N) : "memory");
}

// ---------------------------------------------------------------------------
// Convert fp32 -> fp16 into g_Ah. srcSel: 0 = ext ptr, 1 = g_h0.
// ---------------------------------------------------------------------------
__global__ void convertA_kernel(const float4* __restrict__ srcExt, int srcSel, int n4)
{
    int i = blockIdx.x * 256 + threadIdx.x;
    if (i >= n4) return;
    const float4* src = srcSel ? (const float4*)g_h0 : srcExt;
    float4 v = src[i];
    __half2* hp = (__half2*)(g_Ah + 4 * (size_t)i);
    hp[0] = __half2(__float2half_rn(v.x), __float2half_rn(v.y));
    hp[1] = __half2(__float2half_rn(v.z), __float2half_rn(v.w));
}

// Transpose + convert both W's [K, N=2048] fp32 -> g_Bh[slot] [N, K] fp16
__global__ void convertW2_kernel(const float* __restrict__ Wf,
                                 const float* __restrict__ Wb, int K)
{
    int slot = blockIdx.y;
    const float* W = slot ? Wb : Wf;
    int idx = blockIdx.x * 256 + threadIdx.x;      // over K*2048
    if (idx >= K * G_) return;
    int k = idx >> 11;
    int n = idx & 2047;
    g_Bh[slot][(size_t)n * K + k] = __float2half_rn(W[idx]);
}

// ---------------------------------------------------------------------------
// cp.async double-buffered single-pass fp16 mma GEMM (proven core).
// gridDim.z = 2 runs fwd/bwd in one launch. 128x128 tile, BK=32, 8 warps.
// ---------------------------------------------------------------------------
constexpr int TILE_B   = 128 * 80;        // 10240 bytes per tile
constexpr int STAGE_B  = 2 * TILE_B;      // 20480
constexpr int GEMM_SMEM_B = 2 * STAGE_B;  // 40960 (<48KB, no opt-in needed)

__device__ __forceinline__ void stage_loads(
    uint32_t sbase, const __half* __restrict__ Bp,
    int bm, int bn, int K, int k0, int tid)
{
    #pragma unroll
    for (int it = 0; it < 2; it++) {
        int idx = tid + it * 256;          // 0..511 granules of 16B per tile
        int r = idx >> 2, q = idx & 3;
        uint32_t d = sbase + (uint32_t)(r * 80 + q * 16);
        cp_async16(d + 0 * TILE_B, g_Ah + (size_t)(bm + r) * K + k0 + q * 8);
        cp_async16(d + 1 * TILE_B, Bp   + (size_t)(bn + r) * K + k0 + q * 8);
    }
}

__global__ __launch_bounds__(256) void gemm_mma_kernel(
    const float* __restrict__ bias_f, const float* __restrict__ bias_b, int K)
{
    extern __shared__ char dsm[];
    const uint32_t sb = smem_u32(dsm);

    const int bslot = blockIdx.z;
    const float* bias = bslot ? bias_b : bias_f;
    const int tid = threadIdx.x;
    const int wid = tid >> 5, lane = tid & 31;
    const int warp_m = wid >> 2;          // 0..1
    const int warp_n = wid & 3;           // 0..3
    const int bn = blockIdx.x * 128;
    const int bm = blockIdx.y * 128;
    float* C = g_zx + (size_t)bslot * BTG_;
    const __half* Bp = g_Bh[bslot];

    float acc[4][4][4];
    #pragma unroll
    for (int mt = 0; mt < 4; mt++)
        #pragma unroll
        for (int nt = 0; nt < 4; nt++)
            #pragma unroll
            for (int q = 0; q < 4; q++) acc[mt][nt][q] = 0.0f;

    const int a_row = warp_m * 64 + (lane & 15);
    const int a_col = (lane >> 4) * 8;
    const int b_row = warp_n * 32 + (lane & 7) + ((lane >> 4) & 1) * 8;
    const int b_col = ((lane >> 3) & 1) * 8;

    const int nchunk = K / 32;

    stage_loads(sb, Bp, bm, bn, K, 0, tid);
    cp_commit();

    for (int ch = 0; ch < nchunk; ch++) {
        if (ch + 1 < nchunk) {
            stage_loads(sb + ((ch + 1) & 1) * STAGE_B, Bp, bm, bn, K, (ch + 1) * 32, tid);
            cp_commit();
            cp_wait<1>();
        } else {
            cp_wait<0>();
        }
        __syncthreads();

        const uint32_t stg = sb + (ch & 1) * STAGE_B;
        const uint32_t a_b = stg;
        const uint32_t b_b = stg + TILE_B;

        #pragma unroll
        for (int kk = 0; kk < 2; kk++) {
            const int k16 = kk * 16;
            uint32_t af[4][4];
            #pragma unroll
            for (int mt = 0; mt < 4; mt++) {
                uint32_t off = (uint32_t)((a_row + mt * 16) * 40 + k16 + a_col) * 2;
                ldsm_x4(af[mt][0], af[mt][1], af[mt][2], af[mt][3], a_b + off);
            }
            uint32_t bf[4][2];
            #pragma unroll
            for (int np = 0; np < 2; np++) {
                uint32_t off = (uint32_t)((b_row + np * 16) * 40 + k16 + b_col) * 2;
                ldsm_x4(bf[np*2][0], bf[np*2][1], bf[np*2+1][0], bf[np*2+1][1], b_b + off);
            }
            #pragma unroll
            for (int mt = 0; mt < 4; mt++)
                #pragma unroll
                for (int nt = 0; nt < 4; nt++)
                    mma_16816_f16(acc[mt][nt], af[mt], bf[nt][0], bf[nt][1]);
        }
        __syncthreads();
    }

    #pragma unroll
    for (int mt = 0; mt < 4; mt++) {
        const int row0 = bm + warp_m * 64 + mt * 16 + (lane >> 2);
        #pragma unroll
        for (int nt = 0; nt < 4; nt++) {
            const int col = bn + warp_n * 32 + nt * 8 + (lane & 3) * 2;
            const float bv0 = bias[col], bv1 = bias[col + 1];
            float2 v0, v1;
            v0.x = acc[mt][nt][0] + bv0; v0.y = acc[mt][nt][1] + bv1;
            v1.x = acc[mt][nt][2] + bv0; v1.y = acc[mt][nt][3] + bv1;
            *(float2*)&C[(size_t)row0 * G_ + col]       = v0;
            *(float2*)&C[(size_t)(row0 + 8) * G_ + col] = v1;
        }
    }
}

// ---------------------------------------------------------------------------
// Persistent recurrent kernel — R12 structure (4x128 rolling pipeline,
// z smem exchange, b=tid>>3 pointwise mapping) with:
//  * h state single fp16 (halves a-side ldsm + h cp.async + h stores)
//  * U as fp16 hi + 2048-scaled fp16 lo, 2-pass mma with separate correction
//    accumulator folded as z = acc + accL * 2^-11
//  * split-phase grid barrier: arrive -> prefetch next zx gates -> wait
// Grid (64 jt, 2 dir), 256 threads = 8 warps as 4m x 2n.
// ---------------------------------------------------------------------------
constexpr int U_ST = 520;                         // U smem stride (elements)
constexpr int H_ST = 136;                         // h chunk stride (elements)
constexpr int U_COPY_B  = 32 * U_ST * 2;          // 33280 (one of hi/lo)
constexpr int H_STAGE_B = 64 * H_ST * 2;          // 17408 (single fp16)
constexpr int SM_H = 2 * U_COPY_B;                // 66560
constexpr int SM_Z = SM_H + 2 * H_STAGE_B;        // 101376
constexpr int LSTM_SMEM_B = SM_Z + 64 * 36 * 4;   // 110592

constexpr float INV2048 = 1.0f / 2048.0f;

__device__ __forceinline__ void issue_h(
    uint32_t dst_base, const __half* __restrict__ hp, int ck, int tid)
{
    #pragma unroll
    for (int it = 0; it < 4; it++) {
        int idx = tid + it * 256;            // 0..1023
        int row = idx >> 4, g = idx & 15;    // 16 granules x 16B = 128 fp16/row
        cp_async16(dst_base + (uint32_t)(row * 272 + g * 16),
                   hp + (size_t)row * H_ + ck * 128 + g * 8);
    }
}

__global__ __launch_bounds__(256) void lstm_seq_kernel(
    const float* __restrict__ Uf, const float* __restrict__ Ub,
    float* __restrict__ outp)
{
    extern __shared__ char sm[];
    const uint32_t sb = smem_u32(sm);
    const int dir = blockIdx.y;
    const int jt  = blockIdx.x;
    const int tid = threadIdx.x;
    const int wid = tid >> 5, lane = tid & 31;
    const int warp_m = wid >> 1;             // 0..3 (16 batch rows each)
    const int warp_n = wid & 1;              // 0..1 (16 c-cols each)

    __half* Uhi_s = (__half*)sm;
    __half* Ulo_s = Uhi_s + 32 * U_ST;
    float* z_s = (float*)(sm + SM_Z);
    const uint32_t u_hi = sb;
    const uint32_t u_lo = sb + U_COPY_B;
    const uint32_t h_b  = sb + SM_H;

    const float* U_raw = dir ? Ub : Uf;
    float* out = outp ? outp : g_h0;
    const float* zx_d = g_zx + (size_t)dir * BTG_;

    // One-time: U -> smem fp16 hi + scaled lo, layout [c][k], c = gate*8+jj
    #pragma unroll 4
    for (int p = 0; p < 64; p++) {
        int idx = tid + p * 256;             // k*32 + c over 512*32
        int k = idx >> 5, c = idx & 31;
        int gate = c >> 3, jl = c & 7;
        float v = U_raw[(size_t)k * G_ + gate * H_ + jt * 8 + jl];
        __half h = __float2half_rn(v);
        Uhi_s[c * U_ST + k] = h;
        Ulo_s[c * U_ST + k] = __float2half_rn((v - __half2float(h)) * 2048.0f);
    }
    // Zero own slice of h ping slot 0
    for (int i = tid; i < 512; i += 256) {
        int b = i >> 3, jl = i & 7;
        g_hh[dir][0][b * H_ + jt * 8 + jl] = __float2half_rn(0.0f);
    }
    __syncthreads();
    // Full initial barrier
    {
        __syncthreads();
        if (tid == 0) {
            unsigned gen = g_bar_ph[dir][0];
            __threadfence();
            if (atomicAdd(&g_bar_cnt[dir][0], 1u) == 63u) {
                g_bar_cnt[dir][0] = 0;
                __threadfence();
                g_bar_ph[dir][0] = gen + 1u;
            } else {
                while (g_bar_ph[dir][0] == gen) __nanosleep(32);
                __threadfence();
            }
        }
        __syncthreads();
    }

    const int bb = tid >> 3;                 // 0..31 (pointwise rows bb, bb+32)
    const int jj = tid & 7;
    const int j = jt * 8 + jj;
    float creg[2] = {0.0f, 0.0f};

    // ldmatrix lane addressing (element units)
    const int a_row = warp_m * 16 + (lane & 15);
    const int a_col = (lane >> 4) * 8;
    const int b_row = warp_n * 16 + (lane & 7) + ((lane >> 4) & 1) * 8;
    const int b_col = ((lane >> 3) & 1) * 8;

    // Preload zx gates for t = 0
    float zpre[2][4];
    {
        const int tt0 = dir ? (T_ - 1) : 0;
        #pragma unroll
        for (int r = 0; r < 2; r++) {
            const float* zp = zx_d + ((size_t)(bb + r * 32) * T_ + tt0) * G_;
            #pragma unroll
            for (int g = 0; g < 4; g++) zpre[r][g] = zp[g * H_ + j];
        }
    }

    for (int t = 0; t < T_; t++) {
        const int tt = dir ? (T_ - 1 - t) : t;
        const int ping = t & 1, pnext = ping ^ 1;
        const __half* hp = g_hh[dir][ping];

        issue_h(h_b, hp, 0, tid);
        cp_commit();

        float acc[2][4], accL[2][4];
        #pragma unroll
        for (int nt = 0; nt < 2; nt++)
            #pragma unroll
            for (int q = 0; q < 4; q++) { acc[nt][q] = 0.0f; accL[nt][q] = 0.0f; }

        for (int ck = 0; ck < 4; ck++) {
            if (ck + 1 < 4) {
                issue_h(h_b + ((ck + 1) & 1) * H_STAGE_B, hp, ck + 1, tid);
                cp_commit();
                cp_wait<1>();
            } else {
                cp_wait<0>();
            }
            __syncthreads();

            const uint32_t ha = h_b + (ck & 1) * H_STAGE_B;
            const int kbase = ck * 128;

            #pragma unroll
            for (int ks = 0; ks < 8; ks++) {
                const int k16 = ks * 16;
                const uint32_t aoff = (uint32_t)(a_row * H_ST + k16 + a_col) * 2;
                uint32_t af[4];
                ldsm_x4(af[0], af[1], af[2], af[3], ha + aoff);
                const uint32_t boff =
                    (uint32_t)(b_row * U_ST + kbase + k16 + b_col) * 2;
                uint32_t bh[4], bl[4];
                ldsm_x4(bh[0], bh[1], bh[2], bh[3], u_hi + boff);
                ldsm_x4(bl[0], bl[1], bl[2], bl[3], u_lo + boff);
                mma_16816_f16(acc[0],  af, bh[0], bh[1]);
                mma_16816_f16(acc[1],  af, bh[2], bh[3]);
                mma_16816_f16(accL[0], af, bl[0], bl[1]);
                mma_16816_f16(accL[1], af, bl[2], bl[3]);
            }
            __syncthreads();
        }

        // Exchange z fragments via smem (fold the scaled lo-correction)
        {
            const int r0 = warp_m * 16 + (lane >> 2);
            const int cb = warp_n * 16 + (lane & 3) * 2;
            #pragma unroll
            for (int nt = 0; nt < 2; nt++) {
                const int col = cb + nt * 8;
                float2 v0, v1;
                v0.x = acc[nt][0] + accL[nt][0] * INV2048;
                v0.y = acc[nt][1] + accL[nt][1] * INV2048;
                v1.x = acc[nt][2] + accL[nt][2] * INV2048;
                v1.y = acc[nt][3] + accL[nt][3] * INV2048;
                *(float2*)&z_s[r0 * 36 + col]       = v0;
                *(float2*)&z_s[(r0 + 8) * 36 + col] = v1;
            }
        }
        __syncthreads();

        // Pointwise LSTM update (c in registers, h stored single fp16)
        #pragma unroll
        for (int r = 0; r < 2; r++) {
            const int b = bb + r * 32;
            const float zi = z_s[b * 36 + 0 * 8 + jj] + zpre[r][0];
            const float zf = z_s[b * 36 + 1 * 8 + jj] + zpre[r][1];
            const float zg = z_s[b * 36 + 2 * 8 + jj] + zpre[r][2];
            const float zo = z_s[b * 36 + 3 * 8 + jj] + zpre[r][3];
            const float ig = 1.0f / (1.0f + expf(-zi));
            const float fg = 1.0f / (1.0f + expf(-zf));
            const float gg = tanhf(zg);
            const float og = 1.0f / (1.0f + expf(-zo));
            const float cn = fg * creg[r] + ig * gg;
            const float hn = og * tanhf(cn);
            creg[r] = cn;
            out[((size_t)b * T_ + tt) * (2 * H_) + dir * H_ + j] = hn;
            g_hh[dir][pnext][b * H_ + j] = __float2half_rn(hn);
        }

        // Split-phase grid barrier: arrive, prefetch next zx gates, wait
        __syncthreads();
        unsigned bar_gen = 0;
        if (tid == 0) {
            bar_gen = g_bar_ph[dir][0];
            __threadfence();
            if (atomicAdd(&g_bar_cnt[dir][0], 1u) == 63u) {
                g_bar_cnt[dir][0] = 0;
                __threadfence();
                g_bar_ph[dir][0] = bar_gen + 1u;
            }
        }
        if (t + 1 < T_) {
            const int ttn = dir ? (T_ - 2 - t) : (t + 1);
            #pragma unroll
            for (int r = 0; r < 2; r++) {
                const float* zp = zx_d + ((size_t)(bb + r * 32) * T_ + ttn) * G_;
                #pragma unroll
                for (int g = 0; g < 4; g++) zpre[r][g] = zp[g * H_ + j];
            }
        }
        if (tid == 0) {
            while (g_bar_ph[dir][0] == bar_gen) __nanosleep(32);
            __threadfence();
        }
        __syncthreads();
    }
}

// ---------------------------------------------------------------------------
extern "C" void kernel_launch(void* const* d_in, const int* in_sizes, int n_in,
                              void* d_out, int out_size)
{
    (void)in_sizes; (void)n_in; (void)out_size;
    const float* x   = (const float*)d_in[0];
    const float* W0f = (const float*)d_in[1];
    const float* U0f = (const float*)d_in[2];
    const float* b0f = (const float*)d_in[3];
    const float* W0b = (const float*)d_in[4];
    const float* U0b = (const float*)d_in[5];
    const float* b0b = (const float*)d_in[6];
    const float* W1f = (const float*)d_in[7];
    const float* U1f = (const float*)d_in[8];
    const float* b1f = (const float*)d_in[9];
    const float* W1b = (const float*)d_in[10];
    const float* U1b = (const float*)d_in[11];
    const float* b1b = (const float*)d_in[12];
    float* out = (float*)d_out;

    // Opt-in for 108KB lstm smem (idempotent; not an allocation)
    cudaFuncSetAttribute(lstm_seq_kernel,
                         cudaFuncAttributeMaxDynamicSharedMemorySize, LSTM_SMEM_B);

    dim3 gemmGrid(G_ / 128, BT_ / 128, 2);   // fwd+bwd fused
    dim3 seqGrid(64, 2);

    // ---- Phase 0: layer 0 (input = x, K = 512) ----
    {
        const int n4 = (BT_ * D_) / 4;
        convertA_kernel<<<(n4 + 255) / 256, 256>>>((const float4*)x, 0, n4);
        convertW2_kernel<<<dim3((D_ * G_ + 255) / 256, 2), 256>>>(W0f, W0b, D_);
        gemm_mma_kernel<<<gemmGrid, 256, GEMM_SMEM_B>>>(b0f, b0b, D_);
        lstm_seq_kernel<<<seqGrid, 256, LSTM_SMEM_B>>>(U0f, U0b, (float*)nullptr);
    }

    // ---- Phase 1: layer 1 (input = g_h0, K = 1024) ----
    {
        const int K1 = 2 * H_;
        const int n4 = (BT_ * K1) / 4;
        convertA_kernel<<<(n4 + 255) / 256, 256>>>((const float4*)nullptr, 1, n4);
        convertW2_kernel<<<dim3((K1 * G_ + 255) / 256, 2), 256>>>(W1f, W1b, K1);
        gemm_mma_kernel<<<gemmGrid, 256, GEMM_SMEM_B>>>(b1f, b1b, K1);
        lstm_seq_kernel<<<seqGrid, 256, LSTM_SMEM_B>>>(U1f, U1b, out);
    }
}

// round 16
// speedup vs baseline: 1.3300x; 1.1067x over previous
#include <cuda_runtime.h>
#include <cuda_fp16.h>
#include <math.h>
#include <stddef.h>
#include <stdint.h>

// Problem dims (fixed)
constexpr int B_  = 64;
constexpr int T_  = 512;
constexpr int D_  = 512;
constexpr int H_  = 512;
constexpr int G_  = 2048;              // 4*H gates (i,f,g,o)
constexpr int BT_ = B_ * T_;           // 32768
constexpr size_t BTG_ = (size_t)BT_ * G_;   // 67108864 per direction
constexpr int BH_ = B_ * H_;           // 32768

// Scratch (device globals; referenced ONLY from device code — host-side
// references to __device__ symbols give the host shadow address, the R6 bug).
__device__ float g_zx[2 * 67108864];        // [dir][B*T][G] gate preactivations
__device__ float g_h0[33554432];            // layer-0 output [B][T][2H]

// fp16 single-pass GEMM operands
__device__ __align__(16) __half g_Ah[33554432];      // [M, K<=1024]
__device__ __align__(16) __half g_Bh[2][2097152];    // [slot][N=2048, K<=1024]

// Recurrent h state, single fp16, ping-ponged: [dir][ping][B*H]
__device__ __align__(16) __half g_hh[2][2][32768];

// Per-direction software grid barriers (64 co-resident blocks each; padded)
__device__ unsigned g_bar_cnt[2][32];
__device__ volatile unsigned g_bar_ph[2][32];

// ---------------------------------------------------------------------------
// Baseline-PTX helpers (compute_103-safe: ldmatrix + mma.sync + cp.async)
// ---------------------------------------------------------------------------
__device__ __forceinline__ uint32_t smem_u32(const void* p) {
    uint32_t a;
    asm("{ .reg .u64 t; cvta.to.shared.u64 t, %1; cvt.u32.u64 %0, t; }" : "=r"(a) : "l"(p));
    return a;
}

__device__ __forceinline__ void ldsm_x4(uint32_t& r0, uint32_t& r1,
                                        uint32_t& r2, uint32_t& r3, uint32_t addr)
{
    asm volatile("ldmatrix.sync.aligned.m8n8.x4.shared.b16 {%0,%1,%2,%3}, [%4];"
        : "=r"(r0), "=r"(r1), "=r"(r2), "=r"(r3) : "r"(addr));
}

__device__ __forceinline__ void mma_16816_f16(float* c, const uint32_t* a,
                                              uint32_t b0, uint32_t b1)
{
    asm volatile(
        "mma.sync.aligned.m16n8k16.row.col.f32.f16.f16.f32 "
        "{%0,%1,%2,%3}, {%4,%5,%6,%7}, {%8,%9}, {%0,%1,%2,%3};"
        : "+f"(c[0]), "+f"(c[1]), "+f"(c[2]), "+f"(c[3])
        : "r"(a[0]), "r"(a[1]), "r"(a[2]), "r"(a[3]), "r"(b0), "r"(b1));
}

__device__ __forceinline__ void cp_async16(uint32_t dst, const void* src) {
    asm volatile("cp.async.cg.shared.global [%0], [%1], 16;" :: "r"(dst), "l"(src));
}
__device__ __forceinline__ void cp_commit() {
    asm volatile("cp.async.commit_group;" ::: "memory");
}
template <int N>
__device__ __forceinline__ void cp_wait() {
    asm volatile("cp.async.wait_group %0;" :: "n"(N) : "memory");
}

// ---------------------------------------------------------------------------
// Convert fp32 -> fp16 into g_Ah. srcSel: 0 = ext ptr, 1 = g_h0.
// ---------------------------------------------------------------------------
__global__ void convertA_kernel(const float4* __restrict__ srcExt, int srcSel, int n4)
{
    int i = blockIdx.x * 256 + threadIdx.x;
    if (i >= n4) return;
    const float4* src = srcSel ? (const float4*)g_h0 : srcExt;
    float4 v = src[i];
    __half2* hp = (__half2*)(g_Ah + 4 * (size_t)i);
    hp[0] = __half2(__float2half_rn(v.x), __float2half_rn(v.y));
    hp[1] = __half2(__float2half_rn(v.z), __float2half_rn(v.w));
}

// Transpose + convert both W's [K, N=2048] fp32 -> g_Bh[slot] [N, K] fp16
__global__ void convertW2_kernel(const float* __restrict__ Wf,
                                 const float* __restrict__ Wb, int K)
{
    int slot = blockIdx.y;
    const float* W = slot ? Wb : Wf;
    int idx = blockIdx.x * 256 + threadIdx.x;      // over K*2048
    if (idx >= K * G_) return;
    int k = idx >> 11;
    int n = idx & 2047;
    g_Bh[slot][(size_t)n * K + k] = __float2half_rn(W[idx]);
}

// ---------------------------------------------------------------------------
// cp.async double-buffered single-pass fp16 mma GEMM (proven core).
// gridDim.z = 2 runs fwd/bwd in one launch. 128x128 tile, BK=32, 8 warps.
// ---------------------------------------------------------------------------
constexpr int TILE_B   = 128 * 80;        // 10240 bytes per tile
constexpr int STAGE_B  = 2 * TILE_B;      // 20480
constexpr int GEMM_SMEM_B = 2 * STAGE_B;  // 40960 (<48KB, no opt-in needed)

__device__ __forceinline__ void stage_loads(
    uint32_t sbase, const __half* __restrict__ Bp,
    int bm, int bn, int K, int k0, int tid)
{
    #pragma unroll
    for (int it = 0; it < 2; it++) {
        int idx = tid + it * 256;          // 0..511 granules of 16B per tile
        int r = idx >> 2, q = idx & 3;
        uint32_t d = sbase + (uint32_t)(r * 80 + q * 16);
        cp_async16(d + 0 * TILE_B, g_Ah + (size_t)(bm + r) * K + k0 + q * 8);
        cp_async16(d + 1 * TILE_B, Bp   + (size_t)(bn + r) * K + k0 + q * 8);
    }
}

__global__ __launch_bounds__(256) void gemm_mma_kernel(
    const float* __restrict__ bias_f, const float* __restrict__ bias_b, int K)
{
    extern __shared__ char dsm[];
    const uint32_t sb = smem_u32(dsm);

    const int bslot = blockIdx.z;
    const float* bias = bslot ? bias_b : bias_f;
    const int tid = threadIdx.x;
    const int wid = tid >> 5, lane = tid & 31;
    const int warp_m = wid >> 2;          // 0..1
    const int warp_n = wid & 3;           // 0..3
    const int bn = blockIdx.x * 128;
    const int bm = blockIdx.y * 128;
    float* C = g_zx + (size_t)bslot * BTG_;
    const __half* Bp = g_Bh[bslot];

    float acc[4][4][4];
    #pragma unroll
    for (int mt = 0; mt < 4; mt++)
        #pragma unroll
        for (int nt = 0; nt < 4; nt++)
            #pragma unroll
            for (int q = 0; q < 4; q++) acc[mt][nt][q] = 0.0f;

    const int a_row = warp_m * 64 + (lane & 15);
    const int a_col = (lane >> 4) * 8;
    const int b_row = warp_n * 32 + (lane & 7) + ((lane >> 4) & 1) * 8;
    const int b_col = ((lane >> 3) & 1) * 8;

    const int nchunk = K / 32;

    stage_loads(sb, Bp, bm, bn, K, 0, tid);
    cp_commit();

    for (int ch = 0; ch < nchunk; ch++) {
        if (ch + 1 < nchunk) {
            stage_loads(sb + ((ch + 1) & 1) * STAGE_B, Bp, bm, bn, K, (ch + 1) * 32, tid);
            cp_commit();
            cp_wait<1>();
        } else {
            cp_wait<0>();
        }
        __syncthreads();

        const uint32_t stg = sb + (ch & 1) * STAGE_B;
        const uint32_t a_b = stg;
        const uint32_t b_b = stg + TILE_B;

        #pragma unroll
        for (int kk = 0; kk < 2; kk++) {
            const int k16 = kk * 16;
            uint32_t af[4][4];
            #pragma unroll
            for (int mt = 0; mt < 4; mt++) {
                uint32_t off = (uint32_t)((a_row + mt * 16) * 40 + k16 + a_col) * 2;
                ldsm_x4(af[mt][0], af[mt][1], af[mt][2], af[mt][3], a_b + off);
            }
            uint32_t bf[4][2];
            #pragma unroll
            for (int np = 0; np < 2; np++) {
                uint32_t off = (uint32_t)((b_row + np * 16) * 40 + k16 + b_col) * 2;
                ldsm_x4(bf[np*2][0], bf[np*2][1], bf[np*2+1][0], bf[np*2+1][1], b_b + off);
            }
            #pragma unroll
            for (int mt = 0; mt < 4; mt++)
                #pragma unroll
                for (int nt = 0; nt < 4; nt++)
                    mma_16816_f16(acc[mt][nt], af[mt], bf[nt][0], bf[nt][1]);
        }
        __syncthreads();
    }

    #pragma unroll
    for (int mt = 0; mt < 4; mt++) {
        const int row0 = bm + warp_m * 64 + mt * 16 + (lane >> 2);
        #pragma unroll
        for (int nt = 0; nt < 4; nt++) {
            const int col = bn + warp_n * 32 + nt * 8 + (lane & 3) * 2;
            const float bv0 = bias[col], bv1 = bias[col + 1];
            float2 v0, v1;
            v0.x = acc[mt][nt][0] + bv0; v0.y = acc[mt][nt][1] + bv1;
            v1.x = acc[mt][nt][2] + bv0; v1.y = acc[mt][nt][3] + bv1;
            *(float2*)&C[(size_t)row0 * G_ + col]       = v0;
            *(float2*)&C[(size_t)(row0 + 8) * G_ + col] = v1;
        }
    }
}

// ---------------------------------------------------------------------------
// Persistent recurrent kernel — R15 structure with SINGLE-PASS fp16 U
// (lo-correction dropped; U-quantization error ~2e-5/step, averages out):
//  * h state single fp16; U single fp16 [c][k] resident in smem
//  * 4x128 rolling cp.async h pipeline, z smem exchange
//  * split-phase grid barrier: arrive -> prefetch next zx gates -> wait
// Grid (64 jt, 2 dir), 256 threads = 8 warps as 4m x 2n.
// ---------------------------------------------------------------------------
constexpr int U_ST = 520;                         // U smem stride (elements)
constexpr int H_ST = 136;                         // h chunk stride (elements)
constexpr int U_COPY_B  = 32 * U_ST * 2;          // 33280 (fp16 hi only)
constexpr int H_STAGE_B = 64 * H_ST * 2;          // 17408 (single fp16)
constexpr int SM_H = U_COPY_B;                    // 33280
constexpr int SM_Z = SM_H + 2 * H_STAGE_B;        // 68096
constexpr int LSTM_SMEM_B = SM_Z + 64 * 36 * 4;   // 77312

__device__ __forceinline__ void issue_h(
    uint32_t dst_base, const __half* __restrict__ hp, int ck, int tid)
{
    #pragma unroll
    for (int it = 0; it < 4; it++) {
        int idx = tid + it * 256;            // 0..1023
        int row = idx >> 4, g = idx & 15;    // 16 granules x 16B = 128 fp16/row
        cp_async16(dst_base + (uint32_t)(row * 272 + g * 16),
                   hp + (size_t)row * H_ + ck * 128 + g * 8);
    }
}

__global__ __launch_bounds__(256) void lstm_seq_kernel(
    const float* __restrict__ Uf, const float* __restrict__ Ub,
    float* __restrict__ outp)
{
    extern __shared__ char sm[];
    const uint32_t sb = smem_u32(sm);
    const int dir = blockIdx.y;
    const int jt  = blockIdx.x;
    const int tid = threadIdx.x;
    const int wid = tid >> 5, lane = tid & 31;
    const int warp_m = wid >> 1;             // 0..3 (16 batch rows each)
    const int warp_n = wid & 1;              // 0..1 (16 c-cols each)

    __half* Uhi_s = (__half*)sm;
    float* z_s = (float*)(sm + SM_Z);
    const uint32_t u_hi = sb;
    const uint32_t h_b  = sb + SM_H;

    const float* U_raw = dir ? Ub : Uf;
    float* out = outp ? outp : g_h0;
    const float* zx_d = g_zx + (size_t)dir * BTG_;

    // One-time: U -> smem fp16, layout [c][k], c = gate*8+jj
    #pragma unroll 4
    for (int p = 0; p < 64; p++) {
        int idx = tid + p * 256;             // k*32 + c over 512*32
        int k = idx >> 5, c = idx & 31;
        int gate = c >> 3, jl = c & 7;
        Uhi_s[c * U_ST + k] =
            __float2half_rn(U_raw[(size_t)k * G_ + gate * H_ + jt * 8 + jl]);
    }
    // Zero own slice of h ping slot 0
    for (int i = tid; i < 512; i += 256) {
        int b = i >> 3, jl = i & 7;
        g_hh[dir][0][b * H_ + jt * 8 + jl] = __float2half_rn(0.0f);
    }
    __syncthreads();
    // Full initial barrier
    {
        __syncthreads();
        if (tid == 0) {
            unsigned gen = g_bar_ph[dir][0];
            __threadfence();
            if (atomicAdd(&g_bar_cnt[dir][0], 1u) == 63u) {
                g_bar_cnt[dir][0] = 0;
                __threadfence();
                g_bar_ph[dir][0] = gen + 1u;
            } else {
                while (g_bar_ph[dir][0] == gen) __nanosleep(32);
                __threadfence();
            }
        }
        __syncthreads();
    }

    const int bb = tid >> 3;                 // 0..31 (pointwise rows bb, bb+32)
    const int jj = tid & 7;
    const int j = jt * 8 + jj;
    float creg[2] = {0.0f, 0.0f};

    // ldmatrix lane addressing (element units)
    const int a_row = warp_m * 16 + (lane & 15);
    const int a_col = (lane >> 4) * 8;
    const int b_row = warp_n * 16 + (lane & 7) + ((lane >> 4) & 1) * 8;
    const int b_col = ((lane >> 3) & 1) * 8;

    // Preload zx gates for t = 0
    float zpre[2][4];
    {
        const int tt0 = dir ? (T_ - 1) : 0;
        #pragma unroll
        for (int r = 0; r < 2; r++) {
            const float* zp = zx_d + ((size_t)(bb + r * 32) * T_ + tt0) * G_;
            #pragma unroll
            for (int g = 0; g < 4; g++) zpre[r][g] = zp[g * H_ + j];
        }
    }

    for (int t = 0; t < T_; t++) {
        const int tt = dir ? (T_ - 1 - t) : t;
        const int ping = t & 1, pnext = ping ^ 1;
        const __half* hp = g_hh[dir][ping];

        issue_h(h_b, hp, 0, tid);
        cp_commit();

        float acc[2][4];
        #pragma unroll
        for (int nt = 0; nt < 2; nt++)
            #pragma unroll
            for (int q = 0; q < 4; q++) acc[nt][q] = 0.0f;

        for (int ck = 0; ck < 4; ck++) {
            if (ck + 1 < 4) {
                issue_h(h_b + ((ck + 1) & 1) * H_STAGE_B, hp, ck + 1, tid);
                cp_commit();
                cp_wait<1>();
            } else {
                cp_wait<0>();
            }
            __syncthreads();

            const uint32_t ha = h_b + (ck & 1) * H_STAGE_B;
            const int kbase = ck * 128;

            #pragma unroll
            for (int ks = 0; ks < 8; ks++) {
                const int k16 = ks * 16;
                const uint32_t aoff = (uint32_t)(a_row * H_ST + k16 + a_col) * 2;
                uint32_t af[4];
                ldsm_x4(af[0], af[1], af[2], af[3], ha + aoff);
                const uint32_t boff =
                    (uint32_t)(b_row * U_ST + kbase + k16 + b_col) * 2;
                uint32_t bh[4];
                ldsm_x4(bh[0], bh[1], bh[2], bh[3], u_hi + boff);
                mma_16816_f16(acc[0], af, bh[0], bh[1]);
                mma_16816_f16(acc[1], af, bh[2], bh[3]);
            }
            __syncthreads();
        }

        // Exchange z fragments via smem
        {
            const int r0 = warp_m * 16 + (lane >> 2);
            const int cb = warp_n * 16 + (lane & 3) * 2;
            #pragma unroll
            for (int nt = 0; nt < 2; nt++) {
                const int col = cb + nt * 8;
                float2 v0, v1;
                v0.x = acc[nt][0]; v0.y = acc[nt][1];
                v1.x = acc[nt][2]; v1.y = acc[nt][3];
                *(float2*)&z_s[r0 * 36 + col]       = v0;
                *(float2*)&z_s[(r0 + 8) * 36 + col] = v1;
            }
        }
        __syncthreads();

        // Pointwise LSTM update (c in registers, h stored single fp16)
        #pragma unroll
        for (int r = 0; r < 2; r++) {
            const int b = bb + r * 32;
            const float zi = z_s[b * 36 + 0 * 8 + jj] + zpre[r][0];
            const float zf = z_s[b * 36 + 1 * 8 + jj] + zpre[r][1];
            const float zg = z_s[b * 36 + 2 * 8 + jj] + zpre[r][2];
            const float zo = z_s[b * 36 + 3 * 8 + jj] + zpre[r][3];
            const float ig = 1.0f / (1.0f + expf(-zi));
            const float fg = 1.0f / (1.0f + expf(-zf));
            const float gg = tanhf(zg);
            const float og = 1.0f / (1.0f + expf(-zo));
            const float cn = fg * creg[r] + ig * gg;
            const float hn = og * tanhf(cn);
            creg[r] = cn;
            out[((size_t)b * T_ + tt) * (2 * H_) + dir * H_ + j] = hn;
            g_hh[dir][pnext][b * H_ + j] = __float2half_rn(hn);
        }

        // Split-phase grid barrier: arrive, prefetch next zx gates, wait
        __syncthreads();
        unsigned bar_gen = 0;
        if (tid == 0) {
            bar_gen = g_bar_ph[dir][0];
            __threadfence();
            if (atomicAdd(&g_bar_cnt[dir][0], 1u) == 63u) {
                g_bar_cnt[dir][0] = 0;
                __threadfence();
                g_bar_ph[dir][0] = bar_gen + 1u;
            }
        }
        if (t + 1 < T_) {
            const int ttn = dir ? (T_ - 2 - t) : (t + 1);
            #pragma unroll
            for (int r = 0; r < 2; r++) {
                const float* zp = zx_d + ((size_t)(bb + r * 32) * T_ + ttn) * G_;
                #pragma unroll
                for (int g = 0; g < 4; g++) zpre[r][g] = zp[g * H_ + j];
            }
        }
        if (tid == 0) {
            while (g_bar_ph[dir][0] == bar_gen) __nanosleep(32);
            __threadfence();
        }
        __syncthreads();
    }
}

// ---------------------------------------------------------------------------
extern "C" void kernel_launch(void* const* d_in, const int* in_sizes, int n_in,
                              void* d_out, int out_size)
{
    (void)in_sizes; (void)n_in; (void)out_size;
    const float* x   = (const float*)d_in[0];
    const float* W0f = (const float*)d_in[1];
    const float* U0f = (const float*)d_in[2];
    const float* b0f = (const float*)d_in[3];
    const float* W0b = (const float*)d_in[4];
    const float* U0b = (const float*)d_in[5];
    const float* b0b = (const float*)d_in[6];
    const float* W1f = (const float*)d_in[7];
    const float* U1f = (const float*)d_in[8];
    const float* b1f = (const float*)d_in[9];
    const float* W1b = (const float*)d_in[10];
    const float* U1b = (const float*)d_in[11];
    const float* b1b = (const float*)d_in[12];
    float* out = (float*)d_out;

    // Opt-in for 76KB lstm smem (idempotent; not an allocation)
    cudaFuncSetAttribute(lstm_seq_kernel,
                         cudaFuncAttributeMaxDynamicSharedMemorySize, LSTM_SMEM_B);

    dim3 gemmGrid(G_ / 128, BT_ / 128, 2);   // fwd+bwd fused
    dim3 seqGrid(64, 2);

    // ---- Phase 0: layer 0 (input = x, K = 512) ----
    {
        const int n4 = (BT_ * D_) / 4;
        convertA_kernel<<<(n4 + 255) / 256, 256>>>((const float4*)x, 0, n4);
        convertW2_kernel<<<dim3((D_ * G_ + 255) / 256, 2), 256>>>(W0f, W0b, D_);
        gemm_mma_kernel<<<gemmGrid, 256, GEMM_SMEM_B>>>(b0f, b0b, D_);
        lstm_seq_kernel<<<seqGrid, 256, LSTM_SMEM_B>>>(U0f, U0b, (float*)nullptr);
    }

    // ---- Phase 1: layer 1 (input = g_h0, K = 1024) ----
    {
        const int K1 = 2 * H_;
        const int n4 = (BT_ * K1) / 4;
        convertA_kernel<<<(n4 + 255) / 256, 256>>>((const float4*)nullptr, 1, n4);
        convertW2_kernel<<<dim3((K1 * G_ + 255) / 256, 2), 256>>>(W1f, W1b, K1);
        gemm_mma_kernel<<<gemmGrid, 256, GEMM_SMEM_B>>>(b1f, b1b, K1);
        lstm_seq_kernel<<<seqGrid, 256, LSTM_SMEM_B>>>(U1f, U1b, out);
    }
}